// round 2
// baseline (speedup 1.0000x reference)
#include <cuda_runtime.h>
#include <cstdint>

#define N_TOK 4096
#define INCH  256
#define HEADS 8
#define DHEAD 64
#define PROJ  512

// Scratch (allocation-free rule: __device__ globals)
__device__ float g_qkv[3][HEADS][N_TOK][DHEAD];   // 24 MB
__device__ float g_part[2][N_TOK][DHEAD];         // 2 MB

__device__ __forceinline__ uint32_t f2tf32(float f) {
    uint32_t u;
    asm("cvt.rna.tf32.f32 %0, %1;" : "=r"(u) : "f"(f));
    return u;
}

__device__ __forceinline__ void mma_tf32(float c[4], const uint32_t a[4], const uint32_t b[2]) {
    asm volatile(
        "mma.sync.aligned.m16n8k8.row.col.f32.tf32.tf32.f32 "
        "{%0,%1,%2,%3}, {%4,%5,%6,%7}, {%8,%9}, {%0,%1,%2,%3};"
        : "+f"(c[0]), "+f"(c[1]), "+f"(c[2]), "+f"(c[3])
        : "r"(a[0]), "r"(a[1]), "r"(a[2]), "r"(a[3]), "r"(b[0]), "r"(b[1]));
}

// ---------------------------------------------------------------------------
// Projection: C[m][p] = sum_k X[m][k] * W[p][k] + bias[p]
// Written to g_qkv[which][p/64][m][p%64].
// Block: BM=32 x BP=64, 256 threads (warps 2x4, each 16x16), K-chunks of 32.
// ---------------------------------------------------------------------------
__global__ void proj_kernel(const float* __restrict__ X, const float* __restrict__ W,
                            const float* __restrict__ bias, int which) {
    __shared__ uint32_t Asm[32][36];
    __shared__ uint32_t Wsm[64][36];
    const int m0 = blockIdx.x * 32;
    const int p0 = blockIdx.y * 64;
    const int tid = threadIdx.x;
    const int lane = tid & 31, warp = tid >> 5;
    const int wm = warp & 1, wn = warp >> 1;      // 2 x 4
    const int g = lane >> 2, tg = lane & 3;
    const int r0 = wm * 16 + g;

    float acc[2][4] = {};

    for (int k0 = 0; k0 < INCH; k0 += 32) {
        __syncthreads();
        {   // X chunk 32x32 = 256 float4
            int r = tid >> 3, c4 = tid & 7;
            float4 v = *(const float4*)&X[(m0 + r) * INCH + k0 + c4 * 4];
            Asm[r][c4*4+0] = f2tf32(v.x); Asm[r][c4*4+1] = f2tf32(v.y);
            Asm[r][c4*4+2] = f2tf32(v.z); Asm[r][c4*4+3] = f2tf32(v.w);
        }
        #pragma unroll
        for (int i = 0; i < 2; i++) {  // W chunk 64x32 = 512 float4
            int e = tid + i * 256;
            int r = e >> 3, c4 = e & 7;
            float4 v = *(const float4*)&W[(p0 + r) * INCH + k0 + c4 * 4];
            Wsm[r][c4*4+0] = f2tf32(v.x); Wsm[r][c4*4+1] = f2tf32(v.y);
            Wsm[r][c4*4+2] = f2tf32(v.z); Wsm[r][c4*4+3] = f2tf32(v.w);
        }
        __syncthreads();
        #pragma unroll
        for (int kk = 0; kk < 4; kk++) {
            uint32_t a[4];
            a[0] = Asm[r0][kk*8+tg];     a[1] = Asm[r0+8][kk*8+tg];
            a[2] = Asm[r0][kk*8+tg+4];   a[3] = Asm[r0+8][kk*8+tg+4];
            #pragma unroll
            for (int j = 0; j < 2; j++) {
                int cb = wn * 16 + j * 8;
                uint32_t b[2];
                b[0] = Wsm[cb + g][kk*8+tg];
                b[1] = Wsm[cb + g][kk*8+tg+4];
                mma_tf32(acc[j], a, b);
            }
        }
    }
    #pragma unroll
    for (int j = 0; j < 2; j++) {
        int cbg = p0 + wn * 16 + j * 8;
        #pragma unroll
        for (int i = 0; i < 4; i++) {
            int row = m0 + r0 + ((i >= 2) ? 8 : 0);
            int col = cbg + 2 * tg + (i & 1);
            g_qkv[which][col >> 6][row][col & 63] = acc[j][i] + bias[col];
        }
    }
}

// ---------------------------------------------------------------------------
// Attention: per (query-tile of 64, head-group of 4 heads) flash-style pass.
// 256 threads, warps 4(m) x 2(n); S/O tiles 64x64; key tiles of 64.
// Dynamic smem: Q,K,V,P tiles [64][68] + Z scratch.
// ---------------------------------------------------------------------------
#define STR 68
__global__ void attn_kernel() {
    extern __shared__ float sm[];
    float* Qsm = sm;                 // [64][68]
    float* Ksm = Qsm + 64 * STR;
    float* Vsm = Ksm + 64 * STR;
    float* Psm = Vsm + 64 * STR;
    float* Zp  = Psm + 64 * STR;     // [2][64]
    float* Zs  = Zp + 128;           // [64]

    const int m0 = blockIdx.x * 64;
    const int hg = blockIdx.y;       // heads hg*4 .. hg*4+3
    const int tid = threadIdx.x;
    const int lane = tid & 31, warp = tid >> 5;
    const int wm = warp & 3, wn = warp >> 2;   // 4 x 2
    const int g = lane >> 2, tg = lane & 3;
    const int r0 = wm * 16 + g;

    float outsum[4][4] = {};

    for (int hh = 0; hh < 4; hh++) {
        const int h = hg * 4 + hh;
        __syncthreads();
        // load Q tile 64x64 -> 1024 float4
        #pragma unroll
        for (int i = 0; i < 4; i++) {
            int e = tid + i * 256;
            int r = e >> 4, c4 = e & 15;
            float4 v = *(const float4*)&g_qkv[0][h][m0 + r][c4 * 4];
            float* q = &Qsm[r * STR + c4 * 4];
            q[0] = __uint_as_float(f2tf32(v.x)); q[1] = __uint_as_float(f2tf32(v.y));
            q[2] = __uint_as_float(f2tf32(v.z)); q[3] = __uint_as_float(f2tf32(v.w));
        }

        float oacc[4][4] = {};
        float zacc[2] = {};

        for (int l0 = 0; l0 < N_TOK; l0 += 64) {
            __syncthreads();
            #pragma unroll
            for (int i = 0; i < 4; i++) {
                int e = tid + i * 256;
                int r = e >> 4, c4 = e & 15;
                float4 kv = *(const float4*)&g_qkv[1][h][l0 + r][c4 * 4];
                float* kd = &Ksm[r * STR + c4 * 4];
                kd[0] = __uint_as_float(f2tf32(kv.x)); kd[1] = __uint_as_float(f2tf32(kv.y));
                kd[2] = __uint_as_float(f2tf32(kv.z)); kd[3] = __uint_as_float(f2tf32(kv.w));
                float4 vv = *(const float4*)&g_qkv[2][h][l0 + r][c4 * 4];
                float* vd = &Vsm[r * STR + c4 * 4];
                vd[0] = __uint_as_float(f2tf32(vv.x)); vd[1] = __uint_as_float(f2tf32(vv.y));
                vd[2] = __uint_as_float(f2tf32(vv.z)); vd[3] = __uint_as_float(f2tf32(vv.w));
            }
            __syncthreads();

            // S = Q @ K^T  (warp: rows [wm*16,+16), cols [wn*32,+32))
            float sacc[4][4] = {};
            #pragma unroll
            for (int kk = 0; kk < 8; kk++) {
                uint32_t a[4];
                a[0] = __float_as_uint(Qsm[r0*STR + kk*8+tg]);
                a[1] = __float_as_uint(Qsm[(r0+8)*STR + kk*8+tg]);
                a[2] = __float_as_uint(Qsm[r0*STR + kk*8+tg+4]);
                a[3] = __float_as_uint(Qsm[(r0+8)*STR + kk*8+tg+4]);
                #pragma unroll
                for (int j = 0; j < 4; j++) {
                    int cb = wn * 32 + j * 8;
                    uint32_t b[2];
                    b[0] = __float_as_uint(Ksm[(cb+g)*STR + kk*8+tg]);
                    b[1] = __float_as_uint(Ksm[(cb+g)*STR + kk*8+tg+4]);
                    mma_tf32(sacc[j], a, b);
                }
            }
            // sigmoid -> P, accumulate Z
            #pragma unroll
            for (int j = 0; j < 4; j++) {
                int cb = wn * 32 + j * 8;
                #pragma unroll
                for (int i = 0; i < 4; i++) {
                    float p = 1.f / (1.f + __expf(-sacc[j][i]));
                    zacc[i >> 1] += p;
                    int row = (i < 2) ? r0 : r0 + 8;
                    int col = cb + 2 * tg + (i & 1);
                    Psm[row * STR + col] = __uint_as_float(f2tf32(p));
                }
            }
            __syncthreads();

            // O += P @ V
            #pragma unroll
            for (int kk = 0; kk < 8; kk++) {
                uint32_t a[4];
                a[0] = __float_as_uint(Psm[r0*STR + kk*8+tg]);
                a[1] = __float_as_uint(Psm[(r0+8)*STR + kk*8+tg]);
                a[2] = __float_as_uint(Psm[r0*STR + kk*8+tg+4]);
                a[3] = __float_as_uint(Psm[(r0+8)*STR + kk*8+tg+4]);
                #pragma unroll
                for (int j = 0; j < 4; j++) {
                    int cb = wn * 32 + j * 8;
                    uint32_t b[2];
                    b[0] = __float_as_uint(Vsm[(kk*8+tg)*STR + cb+g]);
                    b[1] = __float_as_uint(Vsm[(kk*8+tg+4)*STR + cb+g]);
                    mma_tf32(oacc[j], a, b);
                }
            }
        }

        // reduce Z over tg (4 lanes) and over wn (2 warps)
        float z0 = zacc[0], z1 = zacc[1];
        z0 += __shfl_xor_sync(0xffffffff, z0, 1);
        z0 += __shfl_xor_sync(0xffffffff, z0, 2);
        z1 += __shfl_xor_sync(0xffffffff, z1, 1);
        z1 += __shfl_xor_sync(0xffffffff, z1, 2);
        __syncthreads();
        if (tg == 0) { Zp[wn*64 + r0] = z0; Zp[wn*64 + r0 + 8] = z1; }
        __syncthreads();
        if (tid < 64) Zs[tid] = Zp[tid] + Zp[64 + tid];
        __syncthreads();

        float zr0 = 1.f / Zs[r0], zr1 = 1.f / Zs[r0 + 8];
        #pragma unroll
        for (int j = 0; j < 4; j++) {
            outsum[j][0] += oacc[j][0] * zr0;
            outsum[j][1] += oacc[j][1] * zr0;
            outsum[j][2] += oacc[j][2] * zr1;
            outsum[j][3] += oacc[j][3] * zr1;
        }
    }

    #pragma unroll
    for (int j = 0; j < 4; j++) {
        int cb = wn * 32 + j * 8;
        #pragma unroll
        for (int i = 0; i < 4; i++) {
            int row = m0 + ((i < 2) ? r0 : r0 + 8);
            int col = cb + 2 * tg + (i & 1);
            g_part[hg][row][col] = outsum[j][i];
        }
    }
}

// ---------------------------------------------------------------------------
// Combine: out = (part0 + part1) / HEADS
// ---------------------------------------------------------------------------
__global__ void combine_kernel(float* __restrict__ out) {
    int i = blockIdx.x * blockDim.x + threadIdx.x;   // float4 index, 65536 total
    const float4* p0 = (const float4*)&g_part[0][0][0];
    const float4* p1 = (const float4*)&g_part[1][0][0];
    float4 a = p0[i], b = p1[i], o;
    o.x = (a.x + b.x) * 0.125f;
    o.y = (a.y + b.y) * 0.125f;
    o.z = (a.z + b.z) * 0.125f;
    o.w = (a.w + b.w) * 0.125f;
    ((float4*)out)[i] = o;
}

extern "C" void kernel_launch(void* const* d_in, const int* in_sizes, int n_in,
                              void* d_out, int out_size) {
    const float* X  = (const float*)d_in[0];
    const float* Wq = (const float*)d_in[1];
    const float* bq = (const float*)d_in[2];
    const float* Wk = (const float*)d_in[3];
    const float* bk = (const float*)d_in[4];
    const float* Wv = (const float*)d_in[5];
    const float* bv = (const float*)d_in[6];
    float* out = (float*)d_out;

    const int attn_smem = (4 * 64 * STR + 192) * (int)sizeof(float);  // 70400 B
    cudaFuncSetAttribute(attn_kernel, cudaFuncAttributeMaxDynamicSharedMemorySize, attn_smem);

    dim3 pg(N_TOK / 32, PROJ / 64);
    proj_kernel<<<pg, 256>>>(X, Wq, bq, 0);
    proj_kernel<<<pg, 256>>>(X, Wk, bk, 1);
    proj_kernel<<<pg, 256>>>(X, Wv, bv, 2);

    dim3 ag(N_TOK / 64, 2);
    attn_kernel<<<ag, 256, attn_smem>>>();

    combine_kernel<<<(N_TOK * DHEAD / 4) / 256, 256>>>(out);
}

// round 5
// speedup vs baseline: 1.9179x; 1.9179x over previous
#include <cuda_runtime.h>
#include <cstdint>

#define N_TOK 4096
#define INCH  256
#define HEADS 8
#define DHEAD 64
#define PROJ  512
#define STR   68

// Scratch (allocation-free rule: __device__ globals)
__device__ float g_qkv[3][HEADS][N_TOK][DHEAD];    // 24 MB (tf32-rounded)
__device__ float g_parts[HEADS][N_TOK][DHEAD];     // 8 MB per-head normalized partials

__device__ __forceinline__ uint32_t f2tf32(float f) {
    uint32_t u;
    asm("cvt.rna.tf32.f32 %0, %1;" : "=r"(u) : "f"(f));
    return u;
}

__device__ __forceinline__ float fast_sigmoid(float x) {
    float t;
    asm("tanh.approx.f32 %0, %1;" : "=f"(t) : "f"(x * 0.5f));
    return fmaf(t, 0.5f, 0.5f);
}

__device__ __forceinline__ void mma_tf32(float c[4], const uint32_t a[4], const uint32_t b[2]) {
    asm volatile(
        "mma.sync.aligned.m16n8k8.row.col.f32.tf32.tf32.f32 "
        "{%0,%1,%2,%3}, {%4,%5,%6,%7}, {%8,%9}, {%0,%1,%2,%3};"
        : "+f"(c[0]), "+f"(c[1]), "+f"(c[2]), "+f"(c[3])
        : "r"(a[0]), "r"(a[1]), "r"(a[2]), "r"(a[3]), "r"(b[0]), "r"(b[1]));
}

// ---------------------------------------------------------------------------
// Projection: C[m][p] = sum_k X[m][k] * W[p][k] + bias[p], tf32-rounded output
// to g_qkv[which][p/64][m][p%64].
// ---------------------------------------------------------------------------
__global__ void proj_kernel(const float* __restrict__ X, const float* __restrict__ W,
                            const float* __restrict__ bias, int which) {
    __shared__ uint32_t Asm[32][36];
    __shared__ uint32_t Wsm[64][36];
    const int m0 = blockIdx.x * 32;
    const int p0 = blockIdx.y * 64;
    const int tid = threadIdx.x;
    const int lane = tid & 31, warp = tid >> 5;
    const int wm = warp & 1, wn = warp >> 1;      // 2 x 4
    const int g = lane >> 2, tg = lane & 3;
    const int r0 = wm * 16 + g;

    float acc[2][4] = {};

    for (int k0 = 0; k0 < INCH; k0 += 32) {
        __syncthreads();
        {   // X chunk 32x32 = 256 float4
            int r = tid >> 3, c4 = tid & 7;
            float4 v = *(const float4*)&X[(m0 + r) * INCH + k0 + c4 * 4];
            Asm[r][c4*4+0] = f2tf32(v.x); Asm[r][c4*4+1] = f2tf32(v.y);
            Asm[r][c4*4+2] = f2tf32(v.z); Asm[r][c4*4+3] = f2tf32(v.w);
        }
        #pragma unroll
        for (int i = 0; i < 2; i++) {  // W chunk 64x32 = 512 float4
            int e = tid + i * 256;
            int r = e >> 3, c4 = e & 7;
            float4 v = *(const float4*)&W[(p0 + r) * INCH + k0 + c4 * 4];
            Wsm[r][c4*4+0] = f2tf32(v.x); Wsm[r][c4*4+1] = f2tf32(v.y);
            Wsm[r][c4*4+2] = f2tf32(v.z); Wsm[r][c4*4+3] = f2tf32(v.w);
        }
        __syncthreads();
        #pragma unroll
        for (int kk = 0; kk < 4; kk++) {
            uint32_t a[4];
            a[0] = Asm[r0][kk*8+tg];     a[1] = Asm[r0+8][kk*8+tg];
            a[2] = Asm[r0][kk*8+tg+4];   a[3] = Asm[r0+8][kk*8+tg+4];
            #pragma unroll
            for (int j = 0; j < 2; j++) {
                int cb = wn * 16 + j * 8;
                uint32_t b[2];
                b[0] = Wsm[cb + g][kk*8+tg];
                b[1] = Wsm[cb + g][kk*8+tg+4];
                mma_tf32(acc[j], a, b);
            }
        }
    }
    #pragma unroll
    for (int j = 0; j < 2; j++) {
        int cbg = p0 + wn * 16 + j * 8;
        #pragma unroll
        for (int i = 0; i < 4; i++) {
            int row = m0 + r0 + ((i >= 2) ? 8 : 0);
            int col = cbg + 2 * tg + (i & 1);
            // pre-round to tf32 so attention never converts in its hot loop
            g_qkv[which][col >> 6][row][col & 63] =
                __uint_as_float(f2tf32(acc[j][i] + bias[col]));
        }
    }
}

// ---------------------------------------------------------------------------
// Attention: one (query-tile 64, head) per CTA. 512 CTAs, 256 threads,
// warps 4(m) x 2(n). Q fragments live in registers for the whole pass.
// smem: K,V,P tiles [64][68] + Z scratch = ~53 KB -> 2 CTAs/SM.
// ---------------------------------------------------------------------------
__global__ __launch_bounds__(256, 2) void attn_kernel() {
    extern __shared__ float sm[];
    float* Ksm = sm;                 // [64][68]
    float* Vsm = Ksm + 64 * STR;
    float* Psm = Vsm + 64 * STR;
    float* Zp  = Psm + 64 * STR;     // [2][64]
    float* Zs  = Zp + 128;           // [64]

    const int m0 = blockIdx.x * 64;
    const int h  = blockIdx.y;
    const int tid = threadIdx.x;
    const int lane = tid & 31, warp = tid >> 5;
    const int wm = warp & 3, wn = warp >> 2;   // 4 x 2
    const int g = lane >> 2, tg = lane & 3;
    const int r0 = wm * 16 + g;

    // Q fragments from gmem once (already tf32-rounded)
    uint32_t qa[8][4];
    {
        const float* Qg = &g_qkv[0][h][m0][0];
        #pragma unroll
        for (int kk = 0; kk < 8; kk++) {
            qa[kk][0] = __float_as_uint(Qg[ r0      * DHEAD + kk*8 + tg    ]);
            qa[kk][1] = __float_as_uint(Qg[(r0 + 8) * DHEAD + kk*8 + tg    ]);
            qa[kk][2] = __float_as_uint(Qg[ r0      * DHEAD + kk*8 + tg + 4]);
            qa[kk][3] = __float_as_uint(Qg[(r0 + 8) * DHEAD + kk*8 + tg + 4]);
        }
    }

    float oacc[4][4] = {};
    float zacc[2] = {};

    for (int l0 = 0; l0 < N_TOK; l0 += 64) {
        __syncthreads();
        #pragma unroll
        for (int i = 0; i < 4; i++) {
            int e = tid + i * 256;
            int r = e >> 4, c4 = e & 15;
            float4 kv = *(const float4*)&g_qkv[1][h][l0 + r][c4 * 4];
            *(float4*)&Ksm[r * STR + c4 * 4] = kv;
            float4 vv = *(const float4*)&g_qkv[2][h][l0 + r][c4 * 4];
            *(float4*)&Vsm[r * STR + c4 * 4] = vv;
        }
        __syncthreads();

        // S = Q @ K^T  (warp: rows [wm*16,+16), cols [wn*32,+32))
        float sacc[4][4] = {};
        #pragma unroll
        for (int kk = 0; kk < 8; kk++) {
            #pragma unroll
            for (int j = 0; j < 4; j++) {
                int cb = wn * 32 + j * 8;
                uint32_t b[2];
                b[0] = __float_as_uint(Ksm[(cb+g)*STR + kk*8+tg]);
                b[1] = __float_as_uint(Ksm[(cb+g)*STR + kk*8+tg+4]);
                mma_tf32(sacc[j], qa[kk], b);
            }
        }
        // sigmoid -> P, accumulate Z
        #pragma unroll
        for (int j = 0; j < 4; j++) {
            int cb = wn * 32 + j * 8;
            #pragma unroll
            for (int i = 0; i < 4; i++) {
                float p = fast_sigmoid(sacc[j][i]);
                zacc[i >> 1] += p;
                int row = (i < 2) ? r0 : r0 + 8;
                int col = cb + 2 * tg + (i & 1);
                Psm[row * STR + col] = __uint_as_float(f2tf32(p));
            }
        }
        __syncthreads();

        // O += P @ V
        #pragma unroll
        for (int kk = 0; kk < 8; kk++) {
            uint32_t a[4];
            a[0] = __float_as_uint(Psm[r0*STR + kk*8+tg]);
            a[1] = __float_as_uint(Psm[(r0+8)*STR + kk*8+tg]);
            a[2] = __float_as_uint(Psm[r0*STR + kk*8+tg+4]);
            a[3] = __float_as_uint(Psm[(r0+8)*STR + kk*8+tg+4]);
            #pragma unroll
            for (int j = 0; j < 4; j++) {
                int cb = wn * 32 + j * 8;
                uint32_t b[2];
                b[0] = __float_as_uint(Vsm[(kk*8+tg)*STR + cb+g]);
                b[1] = __float_as_uint(Vsm[(kk*8+tg+4)*STR + cb+g]);
                mma_tf32(oacc[j], a, b);
            }
        }
    }

    // reduce Z over tg (4 lanes) and over wn (2 warps)
    float z0 = zacc[0], z1 = zacc[1];
    z0 += __shfl_xor_sync(0xffffffff, z0, 1);
    z0 += __shfl_xor_sync(0xffffffff, z0, 2);
    z1 += __shfl_xor_sync(0xffffffff, z1, 1);
    z1 += __shfl_xor_sync(0xffffffff, z1, 2);
    __syncthreads();
    if (tg == 0) { Zp[wn*64 + r0] = z0; Zp[wn*64 + r0 + 8] = z1; }
    __syncthreads();
    if (tid < 64) Zs[tid] = Zp[tid] + Zp[64 + tid];
    __syncthreads();

    float zr0 = 1.f / Zs[r0], zr1 = 1.f / Zs[r0 + 8];

    #pragma unroll
    for (int j = 0; j < 4; j++) {
        int cb = wn * 32 + j * 8;
        #pragma unroll
        for (int i = 0; i < 4; i++) {
            int row = m0 + ((i < 2) ? r0 : r0 + 8);
            int col = cb + 2 * tg + (i & 1);
            float zr = (i < 2) ? zr0 : zr1;
            g_parts[h][row][col] = oacc[j][i] * zr;
        }
    }
}

// ---------------------------------------------------------------------------
// Combine: out = (sum over heads) / HEADS
// ---------------------------------------------------------------------------
__global__ void combine_kernel(float* __restrict__ out) {
    int i = blockIdx.x * blockDim.x + threadIdx.x;   // float4 index, 65536 total
    float4 s = make_float4(0.f, 0.f, 0.f, 0.f);
    #pragma unroll
    for (int h = 0; h < HEADS; h++) {
        float4 a = ((const float4*)&g_parts[h][0][0])[i];
        s.x += a.x; s.y += a.y; s.z += a.z; s.w += a.w;
    }
    float4 o;
    o.x = s.x * 0.125f; o.y = s.y * 0.125f;
    o.z = s.z * 0.125f; o.w = s.w * 0.125f;
    ((float4*)out)[i] = o;
}

extern "C" void kernel_launch(void* const* d_in, const int* in_sizes, int n_in,
                              void* d_out, int out_size) {
    const float* X  = (const float*)d_in[0];
    const float* Wq = (const float*)d_in[1];
    const float* bq = (const float*)d_in[2];
    const float* Wk = (const float*)d_in[3];
    const float* bk = (const float*)d_in[4];
    const float* Wv = (const float*)d_in[5];
    const float* bv = (const float*)d_in[6];
    float* out = (float*)d_out;

    const int attn_smem = (3 * 64 * STR + 192) * (int)sizeof(float);  // ~53 KB
    cudaFuncSetAttribute(attn_kernel, cudaFuncAttributeMaxDynamicSharedMemorySize, attn_smem);

    dim3 pg(N_TOK / 32, PROJ / 64);
    proj_kernel<<<pg, 256>>>(X, Wq, bq, 0);
    proj_kernel<<<pg, 256>>>(X, Wk, bk, 1);
    proj_kernel<<<pg, 256>>>(X, Wv, bv, 2);

    dim3 ag(N_TOK / 64, HEADS);
    attn_kernel<<<ag, 256, attn_smem>>>();

    combine_kernel<<<(N_TOK * DHEAD / 4) / 256, 256>>>(out);
}

// round 7
// speedup vs baseline: 3.4441x; 1.7958x over previous
#include <cuda_runtime.h>
#include <cuda_fp16.h>
#include <cstdint>

#define N_TOK 4096
#define INCH  256
#define HEADS 8
#define DHEAD 64
#define PROJ  512

// Scratch (allocation-free rule: __device__ globals)
__device__ float  g_qk[2][HEADS][N_TOK][DHEAD];      // Q,K tf32-rounded f32 (16 MB)
__device__ __half g_vh[HEADS][N_TOK][DHEAD];         // V fp16 (4 MB)
__device__ float  g_parts2[HEADS][2][N_TOK][DHEAD];  // per (head, wn) partial O (16 MB)
__device__ float  g_zp[HEADS][2][N_TOK];             // per (head, wn) partial Z

__device__ __forceinline__ uint32_t f2tf32(float f) {
    uint32_t u;
    asm("cvt.rna.tf32.f32 %0, %1;" : "=r"(u) : "f"(f));
    return u;
}

__device__ __forceinline__ float fast_sigmoid(float x) {
    float t;
    asm("tanh.approx.f32 %0, %1;" : "=f"(t) : "f"(x * 0.5f));
    return fmaf(t, 0.5f, 0.5f);
}

__device__ __forceinline__ uint32_t pack_f16(float lo, float hi) {
    uint32_t r;
    asm("cvt.rn.f16x2.f32 %0, %1, %2;" : "=r"(r) : "f"(hi), "f"(lo));
    return r;
}

__device__ __forceinline__ void mma_tf32(float c[4], const uint32_t a[4], const uint32_t b[2]) {
    asm volatile(
        "mma.sync.aligned.m16n8k8.row.col.f32.tf32.tf32.f32 "
        "{%0,%1,%2,%3}, {%4,%5,%6,%7}, {%8,%9}, {%0,%1,%2,%3};"
        : "+f"(c[0]), "+f"(c[1]), "+f"(c[2]), "+f"(c[3])
        : "r"(a[0]), "r"(a[1]), "r"(a[2]), "r"(a[3]), "r"(b[0]), "r"(b[1]));
}

__device__ __forceinline__ void mma_f16(float c[4], const uint32_t a[4], uint32_t b0, uint32_t b1) {
    asm volatile(
        "mma.sync.aligned.m16n8k16.row.col.f32.f16.f16.f32 "
        "{%0,%1,%2,%3}, {%4,%5,%6,%7}, {%8,%9}, {%0,%1,%2,%3};"
        : "+f"(c[0]), "+f"(c[1]), "+f"(c[2]), "+f"(c[3])
        : "r"(a[0]), "r"(a[1]), "r"(a[2]), "r"(a[3]), "r"(b0), "r"(b1));
}

__device__ __forceinline__ uint32_t smem_u32(const void* p) {
    uint32_t a;
    asm("{ .reg .u64 t; cvta.to.shared.u64 t, %1; cvt.u32.u64 %0, t; }" : "=r"(a) : "l"(p));
    return a;
}

__device__ __forceinline__ void cpasync16(uint32_t dst, const void* src) {
    asm volatile("cp.async.cg.shared.global [%0], [%1], 16;" :: "r"(dst), "l"(src) : "memory");
}

// ---------------------------------------------------------------------------
// Projection (merged): z = 0,1,2 -> Q,K (tf32 f32), V (fp16).
// C[m][p] = X @ W^T + b. Grid (128, 8, 3) x 256.
// ---------------------------------------------------------------------------
__global__ void proj_kernel(const float* __restrict__ X,
                            const float* __restrict__ Wq, const float* __restrict__ bq,
                            const float* __restrict__ Wk, const float* __restrict__ bk,
                            const float* __restrict__ Wv, const float* __restrict__ bv) {
    const int which = blockIdx.z;
    const float* W    = (which == 0) ? Wq : (which == 1) ? Wk : Wv;
    const float* bias = (which == 0) ? bq : (which == 1) ? bk : bv;

    __shared__ uint32_t Asm[32][36];
    __shared__ uint32_t Wsm[64][36];
    const int m0 = blockIdx.x * 32;
    const int p0 = blockIdx.y * 64;
    const int tid = threadIdx.x;
    const int lane = tid & 31, warp = tid >> 5;
    const int wm = warp & 1, wn = warp >> 1;
    const int g = lane >> 2, tg = lane & 3;
    const int r0 = wm * 16 + g;

    float acc[2][4] = {};

    for (int k0 = 0; k0 < INCH; k0 += 32) {
        __syncthreads();
        {
            int r = tid >> 3, c4 = tid & 7;
            float4 v = *(const float4*)&X[(m0 + r) * INCH + k0 + c4 * 4];
            Asm[r][c4*4+0] = f2tf32(v.x); Asm[r][c4*4+1] = f2tf32(v.y);
            Asm[r][c4*4+2] = f2tf32(v.z); Asm[r][c4*4+3] = f2tf32(v.w);
        }
        #pragma unroll
        for (int i = 0; i < 2; i++) {
            int e = tid + i * 256;
            int r = e >> 3, c4 = e & 7;
            float4 v = *(const float4*)&W[(p0 + r) * INCH + k0 + c4 * 4];
            Wsm[r][c4*4+0] = f2tf32(v.x); Wsm[r][c4*4+1] = f2tf32(v.y);
            Wsm[r][c4*4+2] = f2tf32(v.z); Wsm[r][c4*4+3] = f2tf32(v.w);
        }
        __syncthreads();
        #pragma unroll
        for (int kk = 0; kk < 4; kk++) {
            uint32_t a[4];
            a[0] = Asm[r0][kk*8+tg];     a[1] = Asm[r0+8][kk*8+tg];
            a[2] = Asm[r0][kk*8+tg+4];   a[3] = Asm[r0+8][kk*8+tg+4];
            #pragma unroll
            for (int j = 0; j < 2; j++) {
                int cb = wn * 16 + j * 8;
                uint32_t b[2];
                b[0] = Wsm[cb + g][kk*8+tg];
                b[1] = Wsm[cb + g][kk*8+tg+4];
                mma_tf32(acc[j], a, b);
            }
        }
    }
    #pragma unroll
    for (int j = 0; j < 2; j++) {
        int cbg = p0 + wn * 16 + j * 8;
        #pragma unroll
        for (int i = 0; i < 4; i++) {
            int row = m0 + r0 + ((i >= 2) ? 8 : 0);
            int col = cbg + 2 * tg + (i & 1);
            float val = acc[j][i] + bias[col];
            if (which == 2) {
                g_vh[col >> 6][row][col & 63] = __float2half(val);
            } else {
                g_qk[which][col >> 6][row][col & 63] = __uint_as_float(f2tf32(val));
            }
        }
    }
}

// ---------------------------------------------------------------------------
// Attention: one (query-tile 64, head) per CTA; grid (64, 8), 256 threads,
// warps 4(m) x 2(n). Q frags in regs. S=QK^T tf32; sigmoid+pack fp16 in regs;
// O += P@V via m16n8k16.f16 with V fp16 ldmatrix.trans. cp.async double buffer.
// Each warp accumulates O over its own 32-key slice -> per-wn partials.
// ---------------------------------------------------------------------------
#define K_STG 17408u   // 64 rows * 68 f32 * 4B
#define V_STG 9216u    // 64 rows * 72 f16 * 2B
#define ATTN_SMEM (2 * (K_STG + V_STG))

__global__ __launch_bounds__(256, 2) void attn_kernel() {
    extern __shared__ char smem[];
    const uint32_t sbase = smem_u32(smem);
    const uint32_t sK = sbase;                // K stages at 0, K_STG
    const uint32_t sV = sbase + 2 * K_STG;    // V stages follow

    const int m0 = blockIdx.x * 64;
    const int h  = blockIdx.y;
    const int tid = threadIdx.x;
    const int lane = tid & 31, warp = tid >> 5;
    const int wm = warp & 3, wn = warp >> 2;   // 4 x 2
    const int g = lane >> 2, tg = lane & 3;
    const int r0 = wm * 16 + g;

    // Q fragments (already tf32-rounded)
    uint32_t qa[8][4];
    {
        const float* Qg = &g_qk[0][h][m0][0];
        #pragma unroll
        for (int kk = 0; kk < 8; kk++) {
            qa[kk][0] = __float_as_uint(Qg[ r0      * DHEAD + kk*8 + tg    ]);
            qa[kk][1] = __float_as_uint(Qg[(r0 + 8) * DHEAD + kk*8 + tg    ]);
            qa[kk][2] = __float_as_uint(Qg[ r0      * DHEAD + kk*8 + tg + 4]);
            qa[kk][3] = __float_as_uint(Qg[(r0 + 8) * DHEAD + kk*8 + tg + 4]);
        }
    }

    const float*  Kg = &g_qk[1][h][0][0];
    const __half* Vg = &g_vh[h][0][0];

    // ldmatrix source address (within a V stage): row + group layout
    const int lm_row = (lane & 7) + ((lane >> 3) & 1) * 8;   // k row within 16
    const int lm_col = ((lane >> 4) & 1) * 8;                // n col within 16

    float oacc[8][4] = {};
    float zacc[2] = {};

    // prefetch tile 0
    {
        #pragma unroll
        for (int j = 0; j < 4; j++) {
            int e = tid + j * 256;
            int l = e >> 4, c = e & 15;
            cpasync16(sK + (uint32_t)(l * 272 + c * 16), Kg + l * 64 + c * 4);
        }
        #pragma unroll
        for (int j = 0; j < 2; j++) {
            int e = tid + j * 256;
            int l = e >> 3, c = e & 7;
            cpasync16(sV + (uint32_t)(l * 144 + c * 16), Vg + l * 64 + c * 8);
        }
        asm volatile("cp.async.commit_group;" ::: "memory");
    }

    for (int t = 0; t < N_TOK / 64; ++t) {
        const int stg = t & 1;
        asm volatile("cp.async.wait_group 0;" ::: "memory");
        __syncthreads();

        // prefetch t+1 into other stage (safe: compute(t-1) on it is done)
        if (t + 1 < N_TOK / 64) {
            const float*  Kn = Kg + (t + 1) * 64 * DHEAD;
            const __half* Vn = Vg + (t + 1) * 64 * DHEAD;
            const uint32_t kd = sK + (uint32_t)(1 - stg) * K_STG;
            const uint32_t vd = sV + (uint32_t)(1 - stg) * V_STG;
            #pragma unroll
            for (int j = 0; j < 4; j++) {
                int e = tid + j * 256;
                int l = e >> 4, c = e & 15;
                cpasync16(kd + (uint32_t)(l * 272 + c * 16), Kn + l * 64 + c * 4);
            }
            #pragma unroll
            for (int j = 0; j < 2; j++) {
                int e = tid + j * 256;
                int l = e >> 3, c = e & 7;
                cpasync16(vd + (uint32_t)(l * 144 + c * 16), Vn + l * 64 + c * 8);
            }
            asm volatile("cp.async.commit_group;" ::: "memory");
        }

        const float* Ks = (const float*)(smem + stg * K_STG);
        const uint32_t vb = sV + (uint32_t)stg * V_STG;

        // ---- S = Q @ K^T (tf32), warp cols [wn*32, +32)
        float sacc[4][4] = {};
        #pragma unroll
        for (int kk = 0; kk < 8; kk++) {
            #pragma unroll
            for (int j = 0; j < 4; j++) {
                int cb = wn * 32 + j * 8;
                uint32_t b[2];
                b[0] = __float_as_uint(Ks[(cb + g) * 68 + kk*8 + tg    ]);
                b[1] = __float_as_uint(Ks[(cb + g) * 68 + kk*8 + tg + 4]);
                mma_tf32(sacc[j], qa[kk], b);
            }
        }

        // ---- sigmoid -> P (fp16 A-fragments, in regs), Z accumulation
        uint32_t pf[2][4];
        #pragma unroll
        for (int j = 0; j < 4; j++) {
            float p0 = fast_sigmoid(sacc[j][0]);
            float p1 = fast_sigmoid(sacc[j][1]);
            float p2 = fast_sigmoid(sacc[j][2]);
            float p3 = fast_sigmoid(sacc[j][3]);
            zacc[0] += p0 + p1;
            zacc[1] += p2 + p3;
            pf[j >> 1][(j & 1) * 2 + 0] = pack_f16(p0, p1);
            pf[j >> 1][(j & 1) * 2 + 1] = pack_f16(p2, p3);
        }
        // reorder: A frag = {a0,a1,a2,a3} = {j0(c01), j0(c23), j1(c01), j1(c23)}
        // pf[kc] currently holds [j0c01, j0c23, j1c01, j1c23] -> already correct.

        // ---- O += P @ V (f16 MMA), warp's l-slice = [wn*32 + kc*16, +16)
        #pragma unroll
        for (int kc = 0; kc < 2; kc++) {
            const uint32_t rowb = vb + (uint32_t)((wn * 32 + kc * 16 + lm_row) * 144);
            #pragma unroll
            for (int jp = 0; jp < 4; jp++) {
                uint32_t r0_, r1_, r2_, r3_;
                uint32_t addr = rowb + (uint32_t)((jp * 16 + lm_col) * 2);
                asm volatile(
                    "ldmatrix.sync.aligned.m8n8.x4.trans.shared.b16 {%0,%1,%2,%3}, [%4];"
                    : "=r"(r0_), "=r"(r1_), "=r"(r2_), "=r"(r3_) : "r"(addr));
                mma_f16(oacc[2*jp],     pf[kc], r0_, r1_);
                mma_f16(oacc[2*jp + 1], pf[kc], r2_, r3_);
            }
        }
    }

    // ---- Z reduce within quad, write per-wn partials
    float z0 = zacc[0], z1 = zacc[1];
    z0 += __shfl_xor_sync(0xffffffff, z0, 1);
    z0 += __shfl_xor_sync(0xffffffff, z0, 2);
    z1 += __shfl_xor_sync(0xffffffff, z1, 1);
    z1 += __shfl_xor_sync(0xffffffff, z1, 2);
    if (tg == 0) {
        g_zp[h][wn][m0 + r0]     = z0;
        g_zp[h][wn][m0 + r0 + 8] = z1;
    }

    // ---- O partial store (raw; normalized in combine)
    float* Pd = &g_parts2[h][wn][m0][0];
    #pragma unroll
    for (int jo = 0; jo < 8; jo++) {
        int col = jo * 8 + 2 * tg;
        *(float2*)&Pd[ r0      * DHEAD + col] = make_float2(oacc[jo][0], oacc[jo][1]);
        *(float2*)&Pd[(r0 + 8) * DHEAD + col] = make_float2(oacc[jo][2], oacc[jo][3]);
    }
}

// ---------------------------------------------------------------------------
// Combine: out[n][d] = (1/8) * sum_h (P0+P1)[h][n][d] / (Z0+Z1)[h][n]
// ---------------------------------------------------------------------------
__global__ void combine_kernel(float* __restrict__ out) {
    int i = blockIdx.x * blockDim.x + threadIdx.x;   // float4 idx: 4096*16
    int n = i >> 4, c = i & 15;
    float4 s = make_float4(0.f, 0.f, 0.f, 0.f);
    #pragma unroll
    for (int h = 0; h < HEADS; h++) {
        float inv = 1.f / (g_zp[h][0][n] + g_zp[h][1][n]);
        float4 a = ((const float4*)&g_parts2[h][0][n][0])[c];
        float4 b = ((const float4*)&g_parts2[h][1][n][0])[c];
        s.x += (a.x + b.x) * inv;
        s.y += (a.y + b.y) * inv;
        s.z += (a.z + b.z) * inv;
        s.w += (a.w + b.w) * inv;
    }
    float4 o;
    o.x = s.x * 0.125f; o.y = s.y * 0.125f;
    o.z = s.z * 0.125f; o.w = s.w * 0.125f;
    ((float4*)out)[i] = o;
}

extern "C" void kernel_launch(void* const* d_in, const int* in_sizes, int n_in,
                              void* d_out, int out_size) {
    const float* X  = (const float*)d_in[0];
    const float* Wq = (const float*)d_in[1];
    const float* bq = (const float*)d_in[2];
    const float* Wk = (const float*)d_in[3];
    const float* bk = (const float*)d_in[4];
    const float* Wv = (const float*)d_in[5];
    const float* bv = (const float*)d_in[6];
    float* out = (float*)d_out;

    cudaFuncSetAttribute(attn_kernel, cudaFuncAttributeMaxDynamicSharedMemorySize, ATTN_SMEM);

    dim3 pg(N_TOK / 32, PROJ / 64, 3);
    proj_kernel<<<pg, 256>>>(X, Wq, bq, Wk, bk, Wv, bv);

    dim3 ag(N_TOK / 64, HEADS);
    attn_kernel<<<ag, 256, ATTN_SMEM>>>();

    combine_kernel<<<(N_TOK * DHEAD / 4) / 256, 256>>>(out);
}

// round 8
// speedup vs baseline: 4.8344x; 1.4037x over previous
#include <cuda_runtime.h>
#include <cuda_fp16.h>
#include <cstdint>

#define N_TOK 4096
#define INCH  256
#define HEADS 8
#define DHEAD 64
#define PROJ  512

// Scratch (allocation-free rule: __device__ globals)
__device__ __half g_qh[HEADS][N_TOK][DHEAD];         // Q fp16 (4 MB)
__device__ __half g_kh[HEADS][N_TOK][DHEAD];         // K fp16 (4 MB)
__device__ __half g_vh[HEADS][N_TOK][DHEAD];         // V fp16 (4 MB)
__device__ float  g_parts2[HEADS][2][N_TOK][DHEAD];  // per (head, wn) partial O (16 MB)
__device__ float  g_zp[HEADS][2][N_TOK];             // per (head, wn) partial Z

__device__ __forceinline__ uint32_t f2tf32(float f) {
    uint32_t u;
    asm("cvt.rna.tf32.f32 %0, %1;" : "=r"(u) : "f"(f));
    return u;
}

__device__ __forceinline__ float fast_sigmoid(float x) {
    float t;
    asm("tanh.approx.f32 %0, %1;" : "=f"(t) : "f"(x * 0.5f));
    return fmaf(t, 0.5f, 0.5f);
}

__device__ __forceinline__ uint32_t pack_f16(float lo, float hi) {
    uint32_t r;
    asm("cvt.rn.f16x2.f32 %0, %1, %2;" : "=r"(r) : "f"(hi), "f"(lo));
    return r;
}

__device__ __forceinline__ void mma_tf32(float c[4], const uint32_t a[4], const uint32_t b[2]) {
    asm volatile(
        "mma.sync.aligned.m16n8k8.row.col.f32.tf32.tf32.f32 "
        "{%0,%1,%2,%3}, {%4,%5,%6,%7}, {%8,%9}, {%0,%1,%2,%3};"
        : "+f"(c[0]), "+f"(c[1]), "+f"(c[2]), "+f"(c[3])
        : "r"(a[0]), "r"(a[1]), "r"(a[2]), "r"(a[3]), "r"(b[0]), "r"(b[1]));
}

__device__ __forceinline__ void mma_f16(float c[4], const uint32_t a[4], uint32_t b0, uint32_t b1) {
    asm volatile(
        "mma.sync.aligned.m16n8k16.row.col.f32.f16.f16.f32 "
        "{%0,%1,%2,%3}, {%4,%5,%6,%7}, {%8,%9}, {%0,%1,%2,%3};"
        : "+f"(c[0]), "+f"(c[1]), "+f"(c[2]), "+f"(c[3])
        : "r"(a[0]), "r"(a[1]), "r"(a[2]), "r"(a[3]), "r"(b0), "r"(b1));
}

__device__ __forceinline__ uint32_t smem_u32(const void* p) {
    uint32_t a;
    asm("{ .reg .u64 t; cvta.to.shared.u64 t, %1; cvt.u32.u64 %0, t; }" : "=r"(a) : "l"(p));
    return a;
}

__device__ __forceinline__ void cpasync16(uint32_t dst, const void* src) {
    asm volatile("cp.async.cg.shared.global [%0], [%1], 16;" :: "r"(dst), "l"(src) : "memory");
}

// ---------------------------------------------------------------------------
// Projection (merged): z = 0,1,2 -> Q,K,V all emitted fp16; compute in tf32.
// C[m][p] = X @ W^T + b. Grid (128, 8, 3) x 256.
// ---------------------------------------------------------------------------
__global__ void proj_kernel(const float* __restrict__ X,
                            const float* __restrict__ Wq, const float* __restrict__ bq,
                            const float* __restrict__ Wk, const float* __restrict__ bk,
                            const float* __restrict__ Wv, const float* __restrict__ bv) {
    const int which = blockIdx.z;
    const float* W    = (which == 0) ? Wq : (which == 1) ? Wk : Wv;
    const float* bias = (which == 0) ? bq : (which == 1) ? bk : bv;

    __shared__ uint32_t Asm[32][36];
    __shared__ uint32_t Wsm[64][36];
    const int m0 = blockIdx.x * 32;
    const int p0 = blockIdx.y * 64;
    const int tid = threadIdx.x;
    const int lane = tid & 31, warp = tid >> 5;
    const int wm = warp & 1, wn = warp >> 1;
    const int g = lane >> 2, tg = lane & 3;
    const int r0 = wm * 16 + g;

    float acc[2][4] = {};

    for (int k0 = 0; k0 < INCH; k0 += 32) {
        __syncthreads();
        {
            int r = tid >> 3, c4 = tid & 7;
            float4 v = *(const float4*)&X[(m0 + r) * INCH + k0 + c4 * 4];
            Asm[r][c4*4+0] = f2tf32(v.x); Asm[r][c4*4+1] = f2tf32(v.y);
            Asm[r][c4*4+2] = f2tf32(v.z); Asm[r][c4*4+3] = f2tf32(v.w);
        }
        #pragma unroll
        for (int i = 0; i < 2; i++) {
            int e = tid + i * 256;
            int r = e >> 3, c4 = e & 7;
            float4 v = *(const float4*)&W[(p0 + r) * INCH + k0 + c4 * 4];
            Wsm[r][c4*4+0] = f2tf32(v.x); Wsm[r][c4*4+1] = f2tf32(v.y);
            Wsm[r][c4*4+2] = f2tf32(v.z); Wsm[r][c4*4+3] = f2tf32(v.w);
        }
        __syncthreads();
        #pragma unroll
        for (int kk = 0; kk < 4; kk++) {
            uint32_t a[4];
            a[0] = Asm[r0][kk*8+tg];     a[1] = Asm[r0+8][kk*8+tg];
            a[2] = Asm[r0][kk*8+tg+4];   a[3] = Asm[r0+8][kk*8+tg+4];
            #pragma unroll
            for (int j = 0; j < 2; j++) {
                int cb = wn * 16 + j * 8;
                uint32_t b[2];
                b[0] = Wsm[cb + g][kk*8+tg];
                b[1] = Wsm[cb + g][kk*8+tg+4];
                mma_tf32(acc[j], a, b);
            }
        }
    }
    __half* dst = (which == 0) ? &g_qh[0][0][0] : (which == 1) ? &g_kh[0][0][0]
                                                               : &g_vh[0][0][0];
    #pragma unroll
    for (int j = 0; j < 2; j++) {
        int cbg = p0 + wn * 16 + j * 8;
        #pragma unroll
        for (int i = 0; i < 4; i++) {
            int row = m0 + r0 + ((i >= 2) ? 8 : 0);
            int col = cbg + 2 * tg + (i & 1);
            float val = acc[j][i] + bias[col];
            dst[((col >> 6) * N_TOK + row) * DHEAD + (col & 63)] = __float2half(val);
        }
    }
}

// ---------------------------------------------------------------------------
// Attention: one (query-tile 64, head) per CTA; grid (64, 8), 256 threads,
// warps 4(m) x 2(n). All fp16 operands, f32 accum. K via ldmatrix (non-trans),
// V via ldmatrix.trans. Sigmoid+pack in regs; cp.async double buffer.
// Each warp accumulates O over its own 32-key slice -> per-wn partials.
// ---------------------------------------------------------------------------
#define KV_STG 9216u   // 64 rows * 72 f16 * 2B (144B rows: LDSM conflict-free)
#define ATTN_SMEM (4 * KV_STG)

__global__ __launch_bounds__(256, 2) void attn_kernel() {
    extern __shared__ char smem[];
    const uint32_t sbase = smem_u32(smem);
    const uint32_t sK = sbase;                 // K stages at 0, KV_STG
    const uint32_t sV = sbase + 2 * KV_STG;    // V stages follow

    const int m0 = blockIdx.x * 64;
    const int h  = blockIdx.y;
    const int tid = threadIdx.x;
    const int lane = tid & 31, warp = tid >> 5;
    const int wm = warp & 3, wn = warp >> 2;   // 4 x 2
    const int g = lane >> 2, tg = lane & 3;
    const int r0 = wm * 16 + g;

    // Q fragments fp16: qa[kstep][0..3] for m16n8k16
    uint32_t qa[4][4];
    {
        const __half* Qg = &g_qh[h][m0][0];
        #pragma unroll
        for (int ks = 0; ks < 4; ks++) {
            qa[ks][0] = *(const uint32_t*)&Qg[ r0      * DHEAD + ks*16 + 2*tg    ];
            qa[ks][1] = *(const uint32_t*)&Qg[(r0 + 8) * DHEAD + ks*16 + 2*tg    ];
            qa[ks][2] = *(const uint32_t*)&Qg[ r0      * DHEAD + ks*16 + 2*tg + 8];
            qa[ks][3] = *(const uint32_t*)&Qg[(r0 + 8) * DHEAD + ks*16 + 2*tg + 8];
        }
    }

    const __half* Kg = &g_kh[h][0][0];
    const __half* Vg = &g_vh[h][0][0];

    // ldmatrix lane roles
    const int lm_row = (lane & 7) + ((lane >> 3) & 1) * 8;   // V: k row within 16
    const int lm_col = ((lane >> 4) & 1) * 8;                // V: n col within 16
    const int kb_row = (lane & 7) + ((lane >> 4) & 1) * 8;   // K: n row within 16 (j pair)
    const int kb_col = ((lane >> 3) & 1) * 8;                // K: b0/b1 k-half

    float oacc[8][4] = {};
    float zacc[2] = {};

    // prefetch tile 0 (K and V identical geometry: 64 rows x 64 half)
    {
        #pragma unroll
        for (int j = 0; j < 2; j++) {
            int e = tid + j * 256;
            int l = e >> 3, c = e & 7;
            cpasync16(sK + (uint32_t)(l * 144 + c * 16), Kg + l * 64 + c * 8);
            cpasync16(sV + (uint32_t)(l * 144 + c * 16), Vg + l * 64 + c * 8);
        }
        asm volatile("cp.async.commit_group;" ::: "memory");
    }

    for (int t = 0; t < N_TOK / 64; ++t) {
        const int stg = t & 1;
        asm volatile("cp.async.wait_group 0;" ::: "memory");
        __syncthreads();

        // prefetch t+1 into other stage
        if (t + 1 < N_TOK / 64) {
            const __half* Kn = Kg + (t + 1) * 64 * DHEAD;
            const __half* Vn = Vg + (t + 1) * 64 * DHEAD;
            const uint32_t kd = sK + (uint32_t)(1 - stg) * KV_STG;
            const uint32_t vd = sV + (uint32_t)(1 - stg) * KV_STG;
            #pragma unroll
            for (int j = 0; j < 2; j++) {
                int e = tid + j * 256;
                int l = e >> 3, c = e & 7;
                cpasync16(kd + (uint32_t)(l * 144 + c * 16), Kn + l * 64 + c * 8);
                cpasync16(vd + (uint32_t)(l * 144 + c * 16), Vn + l * 64 + c * 8);
            }
            asm volatile("cp.async.commit_group;" ::: "memory");
        }

        const uint32_t kb = sK + (uint32_t)stg * KV_STG;
        const uint32_t vb = sV + (uint32_t)stg * KV_STG;

        // ---- S = Q @ K^T (fp16 MMA), warp cols [wn*32, +32)
        float sacc[4][4] = {};
        #pragma unroll
        for (int ks = 0; ks < 4; ks++) {
            #pragma unroll
            for (int gi = 0; gi < 2; gi++) {
                // x4: matrices (j=gi*2,b0),(gi*2,b1),(gi*2+1,b0),(gi*2+1,b1)
                uint32_t addr = kb
                    + (uint32_t)((wn * 32 + gi * 16 + kb_row) * 144)
                    + (uint32_t)((ks * 16 + kb_col) * 2);
                uint32_t b0_, b1_, b2_, b3_;
                asm volatile(
                    "ldmatrix.sync.aligned.m8n8.x4.shared.b16 {%0,%1,%2,%3}, [%4];"
                    : "=r"(b0_), "=r"(b1_), "=r"(b2_), "=r"(b3_) : "r"(addr));
                mma_f16(sacc[gi*2],     qa[ks], b0_, b1_);
                mma_f16(sacc[gi*2 + 1], qa[ks], b2_, b3_);
            }
        }

        // ---- sigmoid -> P (fp16 A-fragments in regs), Z accumulation
        uint32_t pf[2][4];
        #pragma unroll
        for (int j = 0; j < 4; j++) {
            float p0 = fast_sigmoid(sacc[j][0]);
            float p1 = fast_sigmoid(sacc[j][1]);
            float p2 = fast_sigmoid(sacc[j][2]);
            float p3 = fast_sigmoid(sacc[j][3]);
            zacc[0] += p0 + p1;
            zacc[1] += p2 + p3;
            pf[j >> 1][(j & 1) * 2 + 0] = pack_f16(p0, p1);
            pf[j >> 1][(j & 1) * 2 + 1] = pack_f16(p2, p3);
        }

        // ---- O += P @ V (fp16 MMA), warp's l-slice = [wn*32 + kc*16, +16)
        #pragma unroll
        for (int kc = 0; kc < 2; kc++) {
            const uint32_t rowb = vb + (uint32_t)((wn * 32 + kc * 16 + lm_row) * 144);
            #pragma unroll
            for (int jp = 0; jp < 4; jp++) {
                uint32_t r0_, r1_, r2_, r3_;
                uint32_t addr = rowb + (uint32_t)((jp * 16 + lm_col) * 2);
                asm volatile(
                    "ldmatrix.sync.aligned.m8n8.x4.trans.shared.b16 {%0,%1,%2,%3}, [%4];"
                    : "=r"(r0_), "=r"(r1_), "=r"(r2_), "=r"(r3_) : "r"(addr));
                mma_f16(oacc[2*jp],     pf[kc], r0_, r1_);
                mma_f16(oacc[2*jp + 1], pf[kc], r2_, r3_);
            }
        }
    }

    // ---- Z reduce within quad, write per-wn partials
    float z0 = zacc[0], z1 = zacc[1];
    z0 += __shfl_xor_sync(0xffffffff, z0, 1);
    z0 += __shfl_xor_sync(0xffffffff, z0, 2);
    z1 += __shfl_xor_sync(0xffffffff, z1, 1);
    z1 += __shfl_xor_sync(0xffffffff, z1, 2);
    if (tg == 0) {
        g_zp[h][wn][m0 + r0]     = z0;
        g_zp[h][wn][m0 + r0 + 8] = z1;
    }

    // ---- O partial store (raw; normalized in combine)
    float* Pd = &g_parts2[h][wn][m0][0];
    #pragma unroll
    for (int jo = 0; jo < 8; jo++) {
        int col = jo * 8 + 2 * tg;
        *(float2*)&Pd[ r0      * DHEAD + col] = make_float2(oacc[jo][0], oacc[jo][1]);
        *(float2*)&Pd[(r0 + 8) * DHEAD + col] = make_float2(oacc[jo][2], oacc[jo][3]);
    }
}

// ---------------------------------------------------------------------------
// Combine: out[n][d] = (1/8) * sum_h (P0+P1)[h][n][d] / (Z0+Z1)[h][n]
// ---------------------------------------------------------------------------
__global__ void combine_kernel(float* __restrict__ out) {
    int i = blockIdx.x * blockDim.x + threadIdx.x;   // float4 idx: 4096*16
    int n = i >> 4, c = i & 15;
    float4 s = make_float4(0.f, 0.f, 0.f, 0.f);
    #pragma unroll
    for (int h = 0; h < HEADS; h++) {
        float inv = 1.f / (g_zp[h][0][n] + g_zp[h][1][n]);
        float4 a = ((const float4*)&g_parts2[h][0][n][0])[c];
        float4 b = ((const float4*)&g_parts2[h][1][n][0])[c];
        s.x += (a.x + b.x) * inv;
        s.y += (a.y + b.y) * inv;
        s.z += (a.z + b.z) * inv;
        s.w += (a.w + b.w) * inv;
    }
    float4 o;
    o.x = s.x * 0.125f; o.y = s.y * 0.125f;
    o.z = s.z * 0.125f; o.w = s.w * 0.125f;
    ((float4*)out)[i] = o;
}

extern "C" void kernel_launch(void* const* d_in, const int* in_sizes, int n_in,
                              void* d_out, int out_size) {
    const float* X  = (const float*)d_in[0];
    const float* Wq = (const float*)d_in[1];
    const float* bq = (const float*)d_in[2];
    const float* Wk = (const float*)d_in[3];
    const float* bk = (const float*)d_in[4];
    const float* Wv = (const float*)d_in[5];
    const float* bv = (const float*)d_in[6];
    float* out = (float*)d_out;

    cudaFuncSetAttribute(attn_kernel, cudaFuncAttributeMaxDynamicSharedMemorySize, ATTN_SMEM);

    dim3 pg(N_TOK / 32, PROJ / 64, 3);
    proj_kernel<<<pg, 256>>>(X, Wq, bq, Wk, bk, Wv, bv);

    dim3 ag(N_TOK / 64, HEADS);
    attn_kernel<<<ag, 256, ATTN_SMEM>>>();

    combine_kernel<<<(N_TOK * DHEAD / 4) / 256, 256>>>(out);
}

// round 9
// speedup vs baseline: 5.2361x; 1.0831x over previous
#include <cuda_runtime.h>
#include <cuda_fp16.h>
#include <cstdint>

#define N_TOK 4096
#define INCH  256
#define HEADS 8
#define DHEAD 64
#define PROJ  512

// Scratch (allocation-free rule: __device__ globals)
__device__ __half g_qh[HEADS][N_TOK][DHEAD];     // Q fp16 (4 MB)
__device__ __half g_kh[HEADS][N_TOK][DHEAD];     // K fp16 (4 MB)
__device__ __half g_vh[HEADS][N_TOK][DHEAD];     // V fp16 (4 MB)
__device__ float  g_parts[HEADS][N_TOK][DHEAD];  // per-head normalized O (8 MB)

__device__ __forceinline__ float fast_sigmoid(float x) {
    float t;
    asm("tanh.approx.f32 %0, %1;" : "=f"(t) : "f"(x * 0.5f));
    return fmaf(t, 0.5f, 0.5f);
}

__device__ __forceinline__ uint32_t pack_f16(float lo, float hi) {
    uint32_t r;
    asm("cvt.rn.f16x2.f32 %0, %1, %2;" : "=r"(r) : "f"(hi), "f"(lo));
    return r;
}

__device__ __forceinline__ void mma_f16(float c[4], const uint32_t a[4], uint32_t b0, uint32_t b1) {
    asm volatile(
        "mma.sync.aligned.m16n8k16.row.col.f32.f16.f16.f32 "
        "{%0,%1,%2,%3}, {%4,%5,%6,%7}, {%8,%9}, {%0,%1,%2,%3};"
        : "+f"(c[0]), "+f"(c[1]), "+f"(c[2]), "+f"(c[3])
        : "r"(a[0]), "r"(a[1]), "r"(a[2]), "r"(a[3]), "r"(b0), "r"(b1));
}

__device__ __forceinline__ uint32_t smem_u32(const void* p) {
    uint32_t a;
    asm("{ .reg .u64 t; cvta.to.shared.u64 t, %1; cvt.u32.u64 %0, t; }" : "=r"(a) : "l"(p));
    return a;
}

__device__ __forceinline__ void cpasync16(uint32_t dst, const void* src) {
    asm volatile("cp.async.cg.shared.global [%0], [%1], 16;" :: "r"(dst), "l"(src) : "memory");
}

// ---------------------------------------------------------------------------
// Projection v2: all-fp16 tensor GEMM (f32 accum). C = X @ W^T + b -> fp16.
// CTA 64(m) x 64(p), K-chunks of 64, warps 4(m) x 2(p). Grid (64, 8, 3).
// smem tiles [64][72] half (144B rows; LDSM conflict-free, proven in attn).
// ---------------------------------------------------------------------------
__global__ __launch_bounds__(256) void proj_kernel(
        const float* __restrict__ X,
        const float* __restrict__ Wq, const float* __restrict__ bq,
        const float* __restrict__ Wk, const float* __restrict__ bk,
        const float* __restrict__ Wv, const float* __restrict__ bv) {
    const int which = blockIdx.z;
    const float* W    = (which == 0) ? Wq : (which == 1) ? Wk : Wv;
    const float* bias = (which == 0) ? bq : (which == 1) ? bk : bv;
    __half* dst = (which == 0) ? &g_qh[0][0][0] : (which == 1) ? &g_kh[0][0][0]
                                                               : &g_vh[0][0][0];

    __shared__ __half Xs[64][72];
    __shared__ __half Ws[64][72];

    const int m0 = blockIdx.x * 64;
    const int p0 = blockIdx.y * 64;
    const int tid = threadIdx.x;
    const int lane = tid & 31, warp = tid >> 5;
    const int wm = warp & 3, wn = warp >> 2;   // 4(m) x 2(p)
    const int g = lane >> 2, tg = lane & 3;

    // ldmatrix lane roles
    const int a_row = lane & 15;                             // A: m row within 16
    const int a_col = (lane >> 4) * 8;                       // A: k col half
    const int kb_row = (lane & 7) + ((lane >> 4) & 1) * 8;   // B: p row within 16
    const int kb_col = ((lane >> 3) & 1) * 8;                // B: k half

    float acc[4][4] = {};

    const int frow = tid >> 2, fq = tid & 3;   // fill mapping: row, 16-col quarter

    for (int k0 = 0; k0 < INCH; k0 += 64) {
        __syncthreads();
        {   // X tile fill: 16 f32 per thread -> 16 half
            const float4* xs = (const float4*)&X[(m0 + frow) * INCH + k0 + fq * 16];
            float4 v0 = xs[0], v1 = xs[1], v2 = xs[2], v3 = xs[3];
            uint4 o0, o1;
            o0.x = pack_f16(v0.x, v0.y); o0.y = pack_f16(v0.z, v0.w);
            o0.z = pack_f16(v1.x, v1.y); o0.w = pack_f16(v1.z, v1.w);
            o1.x = pack_f16(v2.x, v2.y); o1.y = pack_f16(v2.z, v2.w);
            o1.z = pack_f16(v3.x, v3.y); o1.w = pack_f16(v3.z, v3.w);
            *(uint4*)&Xs[frow][fq * 16]     = o0;
            *(uint4*)&Xs[frow][fq * 16 + 8] = o1;
            const float4* ws = (const float4*)&W[(p0 + frow) * INCH + k0 + fq * 16];
            v0 = ws[0]; v1 = ws[1]; v2 = ws[2]; v3 = ws[3];
            o0.x = pack_f16(v0.x, v0.y); o0.y = pack_f16(v0.z, v0.w);
            o0.z = pack_f16(v1.x, v1.y); o0.w = pack_f16(v1.z, v1.w);
            o1.x = pack_f16(v2.x, v2.y); o1.y = pack_f16(v2.z, v2.w);
            o1.z = pack_f16(v3.x, v3.y); o1.w = pack_f16(v3.z, v3.w);
            *(uint4*)&Ws[frow][fq * 16]     = o0;
            *(uint4*)&Ws[frow][fq * 16 + 8] = o1;
        }
        __syncthreads();

        #pragma unroll
        for (int ks = 0; ks < 4; ks++) {
            uint32_t a[4];
            {
                uint32_t addr = smem_u32(&Xs[wm * 16 + a_row][ks * 16 + a_col]);
                asm volatile(
                    "ldmatrix.sync.aligned.m8n8.x4.shared.b16 {%0,%1,%2,%3}, [%4];"
                    : "=r"(a[0]), "=r"(a[1]), "=r"(a[2]), "=r"(a[3]) : "r"(addr));
            }
            #pragma unroll
            for (int gi = 0; gi < 2; gi++) {
                uint32_t addr = smem_u32(&Ws[wn * 32 + gi * 16 + kb_row][ks * 16 + kb_col]);
                uint32_t b0_, b1_, b2_, b3_;
                asm volatile(
                    "ldmatrix.sync.aligned.m8n8.x4.shared.b16 {%0,%1,%2,%3}, [%4];"
                    : "=r"(b0_), "=r"(b1_), "=r"(b2_), "=r"(b3_) : "r"(addr));
                mma_f16(acc[gi*2],     a, b0_, b1_);
                mma_f16(acc[gi*2 + 1], a, b2_, b3_);
            }
        }
    }

    // epilogue: add bias, fp16, store pairs
    #pragma unroll
    for (int j = 0; j < 4; j++) {
        int col = p0 + wn * 32 + j * 8 + 2 * tg;
        float b0 = bias[col], b1 = bias[col + 1];
        int hd = col >> 6, d = col & 63;
        int row0 = m0 + wm * 16 + g;
        *(uint32_t*)&dst[(hd * N_TOK + row0    ) * DHEAD + d] =
            pack_f16(acc[j][0] + b0, acc[j][1] + b1);
        *(uint32_t*)&dst[(hd * N_TOK + row0 + 8) * DHEAD + d] =
            pack_f16(acc[j][2] + b0, acc[j][3] + b1);
    }
}

// ---------------------------------------------------------------------------
// Attention: one (query-tile 64, head) per CTA; grid (64, 8), 256 threads,
// warps 4(m) x 2(n). All fp16 operands, f32 accum. K via ldmatrix (non-trans),
// V via ldmatrix.trans. Sigmoid+pack in regs; cp.async double buffer.
// Epilogue: in-CTA wn reduction + Z normalization via smem reuse.
// ---------------------------------------------------------------------------
#define KV_STG 9216u   // 64 rows * 72 f16 * 2B (144B rows: LDSM conflict-free)
#define ATTN_SMEM (4 * KV_STG)

__global__ __launch_bounds__(256, 2) void attn_kernel() {
    extern __shared__ char smem[];
    const uint32_t sbase = smem_u32(smem);
    const uint32_t sK = sbase;                 // K stages at 0, KV_STG
    const uint32_t sV = sbase + 2 * KV_STG;    // V stages follow

    const int m0 = blockIdx.x * 64;
    const int h  = blockIdx.y;
    const int tid = threadIdx.x;
    const int lane = tid & 31, warp = tid >> 5;
    const int wm = warp & 3, wn = warp >> 2;   // 4 x 2
    const int g = lane >> 2, tg = lane & 3;
    const int r0 = wm * 16 + g;

    // Q fragments fp16: qa[kstep][0..3] for m16n8k16
    uint32_t qa[4][4];
    {
        const __half* Qg = &g_qh[h][m0][0];
        #pragma unroll
        for (int ks = 0; ks < 4; ks++) {
            qa[ks][0] = *(const uint32_t*)&Qg[ r0      * DHEAD + ks*16 + 2*tg    ];
            qa[ks][1] = *(const uint32_t*)&Qg[(r0 + 8) * DHEAD + ks*16 + 2*tg    ];
            qa[ks][2] = *(const uint32_t*)&Qg[ r0      * DHEAD + ks*16 + 2*tg + 8];
            qa[ks][3] = *(const uint32_t*)&Qg[(r0 + 8) * DHEAD + ks*16 + 2*tg + 8];
        }
    }

    const __half* Kg = &g_kh[h][0][0];
    const __half* Vg = &g_vh[h][0][0];

    // ldmatrix lane roles
    const int lm_row = (lane & 7) + ((lane >> 3) & 1) * 8;   // V: k row within 16
    const int lm_col = ((lane >> 4) & 1) * 8;                // V: n col within 16
    const int kb_row = (lane & 7) + ((lane >> 4) & 1) * 8;   // K: n row within 16
    const int kb_col = ((lane >> 3) & 1) * 8;                // K: k half

    float oacc[8][4] = {};
    float zacc[2] = {};

    // prefetch tile 0
    {
        #pragma unroll
        for (int j = 0; j < 2; j++) {
            int e = tid + j * 256;
            int l = e >> 3, c = e & 7;
            cpasync16(sK + (uint32_t)(l * 144 + c * 16), Kg + l * 64 + c * 8);
            cpasync16(sV + (uint32_t)(l * 144 + c * 16), Vg + l * 64 + c * 8);
        }
        asm volatile("cp.async.commit_group;" ::: "memory");
    }

    for (int t = 0; t < N_TOK / 64; ++t) {
        const int stg = t & 1;
        asm volatile("cp.async.wait_group 0;" ::: "memory");
        __syncthreads();

        // prefetch t+1 into other stage
        if (t + 1 < N_TOK / 64) {
            const __half* Kn = Kg + (t + 1) * 64 * DHEAD;
            const __half* Vn = Vg + (t + 1) * 64 * DHEAD;
            const uint32_t kd = sK + (uint32_t)(1 - stg) * KV_STG;
            const uint32_t vd = sV + (uint32_t)(1 - stg) * KV_STG;
            #pragma unroll
            for (int j = 0; j < 2; j++) {
                int e = tid + j * 256;
                int l = e >> 3, c = e & 7;
                cpasync16(kd + (uint32_t)(l * 144 + c * 16), Kn + l * 64 + c * 8);
                cpasync16(vd + (uint32_t)(l * 144 + c * 16), Vn + l * 64 + c * 8);
            }
            asm volatile("cp.async.commit_group;" ::: "memory");
        }

        const uint32_t kb = sK + (uint32_t)stg * KV_STG;
        const uint32_t vb = sV + (uint32_t)stg * KV_STG;

        // ---- S = Q @ K^T (fp16 MMA), warp cols [wn*32, +32)
        float sacc[4][4] = {};
        #pragma unroll
        for (int ks = 0; ks < 4; ks++) {
            #pragma unroll
            for (int gi = 0; gi < 2; gi++) {
                uint32_t addr = kb
                    + (uint32_t)((wn * 32 + gi * 16 + kb_row) * 144)
                    + (uint32_t)((ks * 16 + kb_col) * 2);
                uint32_t b0_, b1_, b2_, b3_;
                asm volatile(
                    "ldmatrix.sync.aligned.m8n8.x4.shared.b16 {%0,%1,%2,%3}, [%4];"
                    : "=r"(b0_), "=r"(b1_), "=r"(b2_), "=r"(b3_) : "r"(addr));
                mma_f16(sacc[gi*2],     qa[ks], b0_, b1_);
                mma_f16(sacc[gi*2 + 1], qa[ks], b2_, b3_);
            }
        }

        // ---- sigmoid -> P (fp16 A-fragments in regs), Z accumulation
        uint32_t pf[2][4];
        #pragma unroll
        for (int j = 0; j < 4; j++) {
            float p0 = fast_sigmoid(sacc[j][0]);
            float p1 = fast_sigmoid(sacc[j][1]);
            float p2 = fast_sigmoid(sacc[j][2]);
            float p3 = fast_sigmoid(sacc[j][3]);
            zacc[0] += p0 + p1;
            zacc[1] += p2 + p3;
            pf[j >> 1][(j & 1) * 2 + 0] = pack_f16(p0, p1);
            pf[j >> 1][(j & 1) * 2 + 1] = pack_f16(p2, p3);
        }

        // ---- O += P @ V (fp16 MMA), warp's l-slice = [wn*32 + kc*16, +16)
        #pragma unroll
        for (int kc = 0; kc < 2; kc++) {
            const uint32_t rowb = vb + (uint32_t)((wn * 32 + kc * 16 + lm_row) * 144);
            #pragma unroll
            for (int jp = 0; jp < 4; jp++) {
                uint32_t r0_, r1_, r2_, r3_;
                uint32_t addr = rowb + (uint32_t)((jp * 16 + lm_col) * 2);
                asm volatile(
                    "ldmatrix.sync.aligned.m8n8.x4.trans.shared.b16 {%0,%1,%2,%3}, [%4];"
                    : "=r"(r0_), "=r"(r1_), "=r"(r2_), "=r"(r3_) : "r"(addr));
                mma_f16(oacc[2*jp],     pf[kc], r0_, r1_);
                mma_f16(oacc[2*jp + 1], pf[kc], r2_, r3_);
            }
        }
    }

    // ================= epilogue: in-CTA reduction + normalize =================
    // Z quad-reduce
    float z0 = zacc[0], z1 = zacc[1];
    z0 += __shfl_xor_sync(0xffffffff, z0, 1);
    z0 += __shfl_xor_sync(0xffffffff, z0, 2);
    z1 += __shfl_xor_sync(0xffffffff, z1, 1);
    z1 += __shfl_xor_sync(0xffffffff, z1, 2);

    __syncthreads();   // main-loop smem dead; safe to reuse
    float* Osm = (float*)smem;                       // [64][68] f32 (17.4 KB)
    float* Zs  = (float*)(smem + 64 * 68 * 4);       // [2][64]
    if (tg == 0) { Zs[wn * 64 + r0] = z0; Zs[wn * 64 + r0 + 8] = z1; }
    if (wn == 1) {
        #pragma unroll
        for (int jo = 0; jo < 8; jo++) {
            int col = jo * 8 + 2 * tg;
            *(float2*)&Osm[ r0      * 68 + col] = make_float2(oacc[jo][0], oacc[jo][1]);
            *(float2*)&Osm[(r0 + 8) * 68 + col] = make_float2(oacc[jo][2], oacc[jo][3]);
        }
    }
    __syncthreads();
    if (wn == 0) {
        float zr0 = 1.f / (Zs[r0]     + Zs[64 + r0]);
        float zr1 = 1.f / (Zs[r0 + 8] + Zs[64 + r0 + 8]);
        float* Pd = &g_parts[h][m0][0];
        #pragma unroll
        for (int jo = 0; jo < 8; jo++) {
            int col = jo * 8 + 2 * tg;
            float2 a0 = *(float2*)&Osm[ r0      * 68 + col];
            float2 a1 = *(float2*)&Osm[(r0 + 8) * 68 + col];
            *(float2*)&Pd[ r0      * DHEAD + col] =
                make_float2((oacc[jo][0] + a0.x) * zr0, (oacc[jo][1] + a0.y) * zr0);
            *(float2*)&Pd[(r0 + 8) * DHEAD + col] =
                make_float2((oacc[jo][2] + a1.x) * zr1, (oacc[jo][3] + a1.y) * zr1);
        }
    }
}

// ---------------------------------------------------------------------------
// Combine: out[n][d] = (1/8) * sum_h parts[h][n][d]
// ---------------------------------------------------------------------------
__global__ void combine_kernel(float* __restrict__ out) {
    int i = blockIdx.x * blockDim.x + threadIdx.x;   // float4 idx: 65536
    float4 s = make_float4(0.f, 0.f, 0.f, 0.f);
    #pragma unroll
    for (int h = 0; h < HEADS; h++) {
        float4 a = ((const float4*)&g_parts[h][0][0])[i];
        s.x += a.x; s.y += a.y; s.z += a.z; s.w += a.w;
    }
    float4 o;
    o.x = s.x * 0.125f; o.y = s.y * 0.125f;
    o.z = s.z * 0.125f; o.w = s.w * 0.125f;
    ((float4*)out)[i] = o;
}

extern "C" void kernel_launch(void* const* d_in, const int* in_sizes, int n_in,
                              void* d_out, int out_size) {
    const float* X  = (const float*)d_in[0];
    const float* Wq = (const float*)d_in[1];
    const float* bq = (const float*)d_in[2];
    const float* Wk = (const float*)d_in[3];
    const float* bk = (const float*)d_in[4];
    const float* Wv = (const float*)d_in[5];
    const float* bv = (const float*)d_in[6];
    float* out = (float*)d_out;

    cudaFuncSetAttribute(attn_kernel, cudaFuncAttributeMaxDynamicSharedMemorySize, ATTN_SMEM);

    dim3 pg(N_TOK / 64, PROJ / 64, 3);
    proj_kernel<<<pg, 256>>>(X, Wq, bq, Wk, bk, Wv, bv);

    dim3 ag(N_TOK / 64, HEADS);
    attn_kernel<<<ag, 256, ATTN_SMEM>>>();

    combine_kernel<<<(N_TOK * DHEAD / 4) / 256, 256>>>(out);
}